// round 4
// baseline (speedup 1.0000x reference)
#include <cuda_runtime.h>
#include <math.h>

#define LOG_HI 4.605170185988092f    // log(100)
#define LOG_LO (-4.605170185988092f) // log(0.01)

typedef unsigned long long u64;

// ---- packed f32x2 helpers (sm_100a FFMA2 path, PTX-only) ----
__device__ __forceinline__ u64 pack2(float lo, float hi) {
    u64 r;
    asm("mov.b64 %0, {%1, %2};" : "=l"(r) : "f"(lo), "f"(hi));
    return r;
}
__device__ __forceinline__ void unpack2(u64 p, float& lo, float& hi) {
    asm("mov.b64 {%0, %1}, %2;" : "=f"(lo), "=f"(hi) : "l"(p));
}
__device__ __forceinline__ void fma2(u64& d, u64 a, u64 b) {
    asm("fma.rn.f32x2 %0, %1, %2, %3;" : "=l"(d) : "l"(a), "l"(b), "l"(d));
}

// ---------------- scratch (device globals; no allocation allowed) ----------------
__device__ float g_cat[256u * 256u * 480u];    // squeeze output
__device__ float g_t0 [256u * 256u * 480u];    // pose0 out
__device__ float g_t1 [256u * 256u * 480u];    // pose1 out
__device__ float g_s1 [256u * 128u * 480u];    // scale1 out
__device__ float g_s2 [256u * 64u  * 480u];    // scale2 out
__device__ float g_pooled[256 * 256];
__device__ float g_bninv[1000];
__device__ float g_proc[256 * 256];            // 0.1 * proc
__device__ float g_t1pool[256 * 256];
__device__ float g_out12[256 * 12];
__device__ float g_sfeat[256 * 64];

// ---------------- squeeze: 1x1 conv 512->256 + ReLU (f32x2) ----------------
// grid (5 ptile, 4 cotile, 256 b), block 256
__global__ void __launch_bounds__(256, 2) squeeze_kernel(const float* __restrict__ f0,
                               const float* __restrict__ w,
                               const float* __restrict__ bias)
{
    const int b  = blockIdx.z;
    const int co0 = blockIdx.y * 64;
    const int p0  = blockIdx.x * 96;
    const int t  = threadIdx.x;
    const int tx = t & 15;       // pos group: 6 cols each
    const int ty = t >> 4;       // co group: 4 co each

    __shared__ float sw[16][65];     // [kk][co]
    __shared__ float sx[16][96];     // [kk][pp]

    u64 acc2[4][3];
#pragma unroll
    for (int i = 0; i < 4; i++)
#pragma unroll
        for (int j = 0; j < 3; j++) acc2[i][j] = 0ull;

    const float* f0b = f0 + (size_t)b * 512u * 480u;

    for (int k0 = 0; k0 < 512; k0 += 16) {
        __syncthreads();
        for (int idx = t; idx < 64 * 16; idx += 256) {
            int co = idx >> 4;
            int kk = idx & 15;
            sw[kk][co] = w[(size_t)(co0 + co) * 512u + k0 + kk];
        }
        for (int idx = t; idx < 16 * 96; idx += 256) {
            int kk = idx / 96;
            int pp = idx % 96;
            sx[kk][pp] = f0b[(size_t)(k0 + kk) * 480u + p0 + pp];
        }
        __syncthreads();
#pragma unroll
        for (int kk = 0; kk < 16; kk++) {
            const float2* xr = reinterpret_cast<const float2*>(&sx[kk][tx * 6]);
            u64 X[3];
#pragma unroll
            for (int j = 0; j < 3; j++) {
                float2 v = xr[j];
                X[j] = pack2(v.x, v.y);
            }
#pragma unroll
            for (int i = 0; i < 4; i++) {
                float wv = sw[kk][ty * 4 + i];
                u64 w2 = pack2(wv, wv);
#pragma unroll
                for (int j = 0; j < 3; j++) fma2(acc2[i][j], w2, X[j]);
            }
        }
    }

#pragma unroll
    for (int i = 0; i < 4; i++) {
        int co = co0 + ty * 4 + i;
        float bb = bias[co];
        float* orow = &g_cat[((size_t)b * 256u + co) * 480u + p0 + tx * 6];
#pragma unroll
        for (int j = 0; j < 3; j++) {
            float a, c;
            unpack2(acc2[i][j], a, c);
            float2 o;
            o.x = fmaxf(a + bb, 0.f);
            o.y = fmaxf(c + bb, 0.f);
            *reinterpret_cast<float2*>(orow + 2 * j) = o;
        }
    }
}

// ---------------- generic mean-over-480 pool (one warp per row) ----------------
__global__ void pool_kernel(const float* __restrict__ src, float* __restrict__ dst, int rows)
{
    int r = blockIdx.x * 8 + (threadIdx.x >> 5);
    int lane = threadIdx.x & 31;
    if (r >= rows) return;
    const float* p = src + (size_t)r * 480u;
    float s = 0.f;
    for (int i = lane; i < 480; i += 32) s += p[i];
#pragma unroll
    for (int o = 16; o > 0; o >>= 1) s += __shfl_xor_sync(0xffffffffu, s, o);
    if (lane == 0) dst[r] = s * (1.0f / 480.0f);
}

// ---------------- feature bank inverse norms ----------------
__global__ void banknorm_kernel(const float* __restrict__ bank)
{
    int r = blockIdx.x * 8 + (threadIdx.x >> 5);
    int lane = threadIdx.x & 31;
    if (r >= 1000) return;
    float s = 0.f;
    for (int c = lane; c < 256; c += 32) {
        float v = bank[(size_t)r * 256u + c];
        s += v * v;
    }
#pragma unroll
    for (int o = 16; o > 0; o >>= 1) s += __shfl_xor_sync(0xffffffffu, s, o);
    if (lane == 0) g_bninv[r] = 1.0f / fmaxf(sqrtf(s), 1e-12f);
}

// ---------------- KNN + fusion MLP: one block per batch row ----------------
__global__ void knn_fusion_kernel(const float* __restrict__ bank,
                                  const float* __restrict__ W1, const float* __restrict__ b1,
                                  const float* __restrict__ W2, const float* __restrict__ b2)
{
    const int b = blockIdx.x;
    const int t = threadIdx.x;
    const int lane = t & 31;
    const int wid = t >> 5;

    __shared__ float q[256];
    __shared__ float sims[1000];
    __shared__ float red[8];
    __shared__ float rv[8]; __shared__ int ri[8];
    __shared__ float topv[5]; __shared__ int topi[5];
    __shared__ float wts[5];
    __shared__ float fused[512];
    __shared__ float h[256];

    q[t] = g_pooled[b * 256 + t];
    __syncthreads();

    float x = q[t] * q[t];
#pragma unroll
    for (int o = 16; o > 0; o >>= 1) x += __shfl_xor_sync(0xffffffffu, x, o);
    if (lane == 0) red[wid] = x;
    __syncthreads();
    if (t == 0) {
        float s = 0.f;
        for (int i = 0; i < 8; i++) s += red[i];
        red[0] = 1.0f / fmaxf(sqrtf(s), 1e-12f);
    }
    __syncthreads();
    const float qinv = red[0];

    for (int r = wid; r < 1000; r += 8) {
        float s = 0.f;
        const float* br = bank + (size_t)r * 256u;
        for (int c = lane; c < 256; c += 32) s += q[c] * br[c];
#pragma unroll
        for (int o = 16; o > 0; o >>= 1) s += __shfl_xor_sync(0xffffffffu, s, o);
        if (lane == 0) sims[r] = s * qinv * g_bninv[r];
    }
    __syncthreads();

    for (int k = 0; k < 5; k++) {
        float bv = -1e30f; int bi = 0x7fffffff;
        for (int r = t; r < 1000; r += 256) {
            float v = sims[r];
            if (v > bv || (v == bv && r < bi)) { bv = v; bi = r; }
        }
#pragma unroll
        for (int o = 16; o > 0; o >>= 1) {
            float ov = __shfl_xor_sync(0xffffffffu, bv, o);
            int oi   = __shfl_xor_sync(0xffffffffu, bi, o);
            if (ov > bv || (ov == bv && oi < bi)) { bv = ov; bi = oi; }
        }
        if (lane == 0) { rv[wid] = bv; ri[wid] = bi; }
        __syncthreads();
        if (t == 0) {
            float mv = rv[0]; int mi = ri[0];
            for (int i = 1; i < 8; i++)
                if (rv[i] > mv || (rv[i] == mv && ri[i] < mi)) { mv = rv[i]; mi = ri[i]; }
            topv[k] = mv; topi[k] = mi;
            sims[mi] = -1e30f;
        }
        __syncthreads();
    }

    if (t == 0) {
        float m = topv[0];
        float s = 0.f;
        for (int k = 0; k < 5; k++) { wts[k] = expf(topv[k] - m); s += wts[k]; }
        float inv = 1.0f / s;
        for (int k = 0; k < 5; k++) wts[k] *= inv;
    }
    __syncthreads();

    fused[t] = q[t];
    {
        float a = 0.f;
#pragma unroll
        for (int k = 0; k < 5; k++) a += wts[k] * bank[(size_t)topi[k] * 256u + t];
        fused[256 + t] = a;
    }
    __syncthreads();

    for (int j = wid; j < 256; j += 8) {
        float s = 0.f;
        const float* wr = W1 + (size_t)j * 512u;
        for (int i = lane; i < 512; i += 32) s += fused[i] * wr[i];
#pragma unroll
        for (int o = 16; o > 0; o >>= 1) s += __shfl_xor_sync(0xffffffffu, s, o);
        if (lane == 0) h[j] = fmaxf(s + b1[j], 0.f);
    }
    __syncthreads();

    for (int j = wid; j < 256; j += 8) {
        float s = 0.f;
        const float* wr = W2 + (size_t)j * 256u;
        for (int i = lane; i < 256; i += 32) s += h[i] * wr[i];
#pragma unroll
        for (int o = 16; o > 0; o >>= 1) s += __shfl_xor_sync(0xffffffffu, s, o);
        if (lane == 0) g_proc[b * 256 + j] = 0.1f * (s + b2[j]);
    }
}

// ---------------- direct 3x3 conv, H=12 W=40, f32x2 inner loop ----------------
// PAD: 0 = zero pad, 1 = reflect pad. ACT: 0 = relu, 1 = elu. ADDPROC: add 0.1*proc[b][ci].
// grid (3 row-tiles, COUT/64, B), block 256.
template <int CIN, int COUT, int ACT, int PAD, bool ADDPROC>
__global__ void __launch_bounds__(256, 2) conv3_kernel(const float* __restrict__ in,
                             const float* __restrict__ w,
                             const float* __restrict__ bias,
                             float* __restrict__ out)
{
    const int b   = blockIdx.z;
    const int co0 = blockIdx.y * 64;
    const int r0  = blockIdx.x * 4;
    const int t   = threadIdx.x;
    const int ty  = t >> 4;        // co group: 4 co each
    const int px  = t & 15;
    const int pr  = px >> 2;       // row within tile (0..3)
    const int pc  = px & 3;        // col group: cols pc*10 .. pc*10+9
    const int row  = r0 + pr;
    const int col0 = pc * 10;

    __shared__ float s_in[8][6][44];   // [ci][row-1..row+4][col -1..40] at idx cc = gc+1
    __shared__ float s_w[64][73];      // [co][ci*9 + ky*3 + kx]

    u64 acc2[4][5];
#pragma unroll
    for (int i = 0; i < 4; i++)
#pragma unroll
        for (int j = 0; j < 5; j++) acc2[i][j] = 0ull;

    const float* inB = in + (size_t)b * CIN * 480u;

    for (int ci0 = 0; ci0 < CIN; ci0 += 8) {
        __syncthreads();
        for (int idx = t; idx < 64 * 72; idx += 256) {
            int co = idx / 72;
            int r  = idx % 72;
            s_w[co][r] = w[((size_t)(co0 + co) * CIN + ci0) * 9u + r];
        }
        for (int idx = t; idx < 8 * 6 * 42; idx += 256) {
            int ci = idx / (6 * 42);
            int rr = (idx / 42) % 6;
            int cc = idx % 42;
            int gr = r0 - 1 + rr;
            int gc = cc - 1;
            float v;
            if (PAD == 0) {
                if (gr < 0 || gr >= 12 || gc < 0 || gc >= 40) {
                    v = 0.f;
                } else {
                    v = inB[(size_t)(ci0 + ci) * 480u + gr * 40 + gc];
                    if (ADDPROC) v += g_proc[b * 256 + ci0 + ci];
                }
            } else {
                if (gr < 0) gr = -gr;
                if (gr >= 12) gr = 22 - gr;
                if (gc < 0) gc = -gc;
                if (gc >= 40) gc = 78 - gc;
                v = inB[(size_t)(ci0 + ci) * 480u + gr * 40 + gc];
                if (ADDPROC) v += g_proc[b * 256 + ci0 + ci];
            }
            s_in[ci][rr][cc] = v;
        }
        __syncthreads();

#pragma unroll
        for (int ci = 0; ci < 8; ci++) {
#pragma unroll
            for (int ky = 0; ky < 3; ky++) {
                // v[0..11] = s_in[ci][pr+ky][col0 .. col0+11], loaded as 6 aligned float2
                const float2* vrow =
                    reinterpret_cast<const float2*>(&s_in[ci][pr + ky][col0]);
                float2 v2[6];
#pragma unroll
                for (int j = 0; j < 6; j++) v2[j] = vrow[j];
                u64 P[6], Q[5];
#pragma unroll
                for (int j = 0; j < 6; j++) P[j] = pack2(v2[j].x, v2[j].y);
#pragma unroll
                for (int j = 0; j < 5; j++) Q[j] = pack2(v2[j].y, v2[j + 1].x);
#pragma unroll
                for (int kx = 0; kx < 3; kx++) {
                    // pair set for this kx (resolved at compile time after unroll)
                    u64 X0 = (kx == 0) ? P[0] : (kx == 1) ? Q[0] : P[1];
                    u64 X1 = (kx == 0) ? P[1] : (kx == 1) ? Q[1] : P[2];
                    u64 X2 = (kx == 0) ? P[2] : (kx == 1) ? Q[2] : P[3];
                    u64 X3 = (kx == 0) ? P[3] : (kx == 1) ? Q[3] : P[4];
                    u64 X4 = (kx == 0) ? P[4] : (kx == 1) ? Q[4] : P[5];
#pragma unroll
                    for (int i = 0; i < 4; i++) {
                        float wv = s_w[ty * 4 + i][ci * 9 + ky * 3 + kx];
                        u64 w2 = pack2(wv, wv);
                        fma2(acc2[i][0], w2, X0);
                        fma2(acc2[i][1], w2, X1);
                        fma2(acc2[i][2], w2, X2);
                        fma2(acc2[i][3], w2, X3);
                        fma2(acc2[i][4], w2, X4);
                    }
                }
            }
        }
    }

    float* outB = out + (size_t)b * COUT * 480u;
#pragma unroll
    for (int i = 0; i < 4; i++) {
        int co = co0 + ty * 4 + i;
        float bb = bias[co];
        float* orow = outB + (size_t)co * 480u + row * 40 + col0;
#pragma unroll
        for (int j = 0; j < 5; j++) {
            float a, c;
            unpack2(acc2[i][j], a, c);
            a += bb; c += bb;
            float2 o;
            if (ACT == 0) {
                o.x = fmaxf(a, 0.f);
                o.y = fmaxf(c, 0.f);
            } else {
                o.x = (a > 0.f) ? a : expm1f(a);
                o.y = (c > 0.f) ? c : expm1f(c);
            }
            *reinterpret_cast<float2*>(orow + 2 * j) = o;
        }
    }
}

// ---------------- pose2 (1x1 conv of pooled t1) ----------------
__global__ void pose2_kernel(const float* __restrict__ w, const float* __restrict__ bias)
{
    int b = blockIdx.x;
    int lane = threadIdx.x;   // block = 32
    const float* tp = g_t1pool + b * 256;
    for (int k = 0; k < 12; k++) {
        float s = 0.f;
        const float* wr = w + (size_t)k * 256u;
        for (int c = lane; c < 256; c += 32) s += tp[c] * wr[c];
#pragma unroll
        for (int o = 16; o > 0; o >>= 1) s += __shfl_xor_sync(0xffffffffu, s, o);
        if (lane == 0) g_out12[b * 12 + k] = s + bias[k];
    }
}

// ---------------- final: scale + pose outputs ----------------
__global__ void final_kernel(const float* __restrict__ lw, const float* __restrict__ lb,
                             float* __restrict__ outbuf)
{
    int b = threadIdx.x;   // 256 threads, 1 block
    float s = 0.f;
    const float* sf = g_sfeat + b * 64;
#pragma unroll
    for (int c = 0; c < 64; c++) s += sf[c] * lw[c];
    s += lb[0];
    float sig = 1.0f / (1.0f + expf(-s));
    float scale = expf(sig * (LOG_HI - LOG_LO) + LOG_LO);

    float* aa = outbuf;           // axisangle: (256,2,1,3)
    float* tr = outbuf + 1536;    // translation: (256,2,1,3)
#pragma unroll
    for (int u = 0; u < 2; u++) {
#pragma unroll
        for (int m = 0; m < 6; m++) {
            float v = 0.001f * g_out12[b * 12 + u * 6 + m] * scale;
            if (m < 3) aa[(b * 2 + u) * 3 + m]       = v;
            else       tr[(b * 2 + u) * 3 + (m - 3)] = v;
        }
    }
    outbuf[3072 + b] = scale;     // scale: (256,1)
}

// ---------------- launch ----------------
extern "C" void kernel_launch(void* const* d_in, const int* in_sizes, int n_in,
                              void* d_out, int out_size)
{
    (void)in_sizes; (void)n_in; (void)out_size;
    const float* f0         = (const float*)d_in[0];
    const float* squeeze_w  = (const float*)d_in[1];
    const float* squeeze_b  = (const float*)d_in[2];
    const float* pose0_w    = (const float*)d_in[3];
    const float* pose0_b    = (const float*)d_in[4];
    const float* pose1_w    = (const float*)d_in[5];
    const float* pose1_b    = (const float*)d_in[6];
    const float* pose2_w    = (const float*)d_in[7];
    const float* pose2_b    = (const float*)d_in[8];
    const float* fusion_w1  = (const float*)d_in[9];
    const float* fusion_b1  = (const float*)d_in[10];
    const float* fusion_w2  = (const float*)d_in[11];
    const float* fusion_b2  = (const float*)d_in[12];
    const float* bank       = (const float*)d_in[13];
    const float* scale_w1   = (const float*)d_in[14];
    const float* scale_b1   = (const float*)d_in[15];
    const float* scale_w2   = (const float*)d_in[16];
    const float* scale_b2   = (const float*)d_in[17];
    const float* scale_lw   = (const float*)d_in[18];
    const float* scale_lb   = (const float*)d_in[19];
    float* out = (float*)d_out;

    void *p_cat, *p_t0, *p_t1, *p_s1, *p_s2;
    cudaGetSymbolAddress(&p_cat, g_cat);
    cudaGetSymbolAddress(&p_t0,  g_t0);
    cudaGetSymbolAddress(&p_t1,  g_t1);
    cudaGetSymbolAddress(&p_s1,  g_s1);
    cudaGetSymbolAddress(&p_s2,  g_s2);
    void *p_pooled, *p_t1pool, *p_sfeat;
    cudaGetSymbolAddress(&p_pooled, g_pooled);
    cudaGetSymbolAddress(&p_t1pool, g_t1pool);
    cudaGetSymbolAddress(&p_sfeat,  g_sfeat);

    // squeeze + pooled
    squeeze_kernel<<<dim3(5, 4, 256), 256>>>(f0, squeeze_w, squeeze_b);
    pool_kernel<<<(65536 + 7) / 8, 256>>>((const float*)p_cat, (float*)p_pooled, 65536);

    // KNN + fusion MLP -> g_proc (= 0.1*proc)
    banknorm_kernel<<<125, 256>>>(bank);
    knn_fusion_kernel<<<256, 256>>>(bank, fusion_w1, fusion_b1, fusion_w2, fusion_b2);

    // pose branch
    conv3_kernel<256, 256, 0, 0, true ><<<dim3(3, 4, 256), 256>>>((const float*)p_cat, pose0_w, pose0_b, (float*)p_t0);
    conv3_kernel<256, 256, 0, 0, false><<<dim3(3, 4, 256), 256>>>((const float*)p_t0, pose1_w, pose1_b, (float*)p_t1);
    pool_kernel<<<(65536 + 7) / 8, 256>>>((const float*)p_t1, (float*)p_t1pool, 65536);
    pose2_kernel<<<256, 32>>>(pose2_w, pose2_b);

    // scale branch
    conv3_kernel<256, 128, 1, 1, true ><<<dim3(3, 2, 256), 256>>>((const float*)p_cat, scale_w1, scale_b1, (float*)p_s1);
    conv3_kernel<128, 64,  1, 1, false><<<dim3(3, 1, 256), 256>>>((const float*)p_s1, scale_w2, scale_b2, (float*)p_s2);
    pool_kernel<<<(16384 + 7) / 8, 256>>>((const float*)p_s2, (float*)p_sfeat, 16384);

    // final assembly
    final_kernel<<<1, 256>>>(scale_lw, scale_lb, out);
}

// round 7
// speedup vs baseline: 1.1758x; 1.1758x over previous
#include <cuda_runtime.h>
#include <cuda_bf16.h>
#include <math.h>
#include <stdint.h>

#define LOG_HI 4.605170185988092f    // log(100)
#define LOG_LO (-4.605170185988092f) // log(0.01)

typedef unsigned int u32;

// ---------------- scratch (device globals; no allocation allowed) ----------------
__device__ float g_cat[256u * 256u * 480u];    // squeeze output
__device__ float g_t0 [256u * 256u * 480u];    // pose0 out
__device__ float g_t1 [256u * 256u * 480u];    // pose1 out
__device__ float g_s1 [256u * 128u * 480u];    // scale1 out
__device__ float g_s2 [256u * 64u  * 480u];    // scale2 out
__device__ float g_pooled[256 * 256];
__device__ float g_bninv[1000];
__device__ float g_proc[256 * 256];            // 0.1 * proc
__device__ float g_t1pool[256 * 256];
__device__ float g_out12[256 * 12];
__device__ float g_sfeat[256 * 64];

// ---------------- mma.sync helpers (sm_80 baseline ISA; works on compute_100) ----------------
__device__ __forceinline__ u32 smem_u32(const void* p) {
    u32 a;
    asm("{ .reg .u64 t; cvta.to.shared.u64 t, %1; cvt.u32.u64 %0, t; }"
        : "=r"(a) : "l"(p));
    return a;
}
__device__ __forceinline__ void ldsm_x4(u32& r0, u32& r1, u32& r2, u32& r3, u32 addr) {
    asm volatile("ldmatrix.sync.aligned.m8n8.x4.shared.b16 {%0,%1,%2,%3}, [%4];"
                 : "=r"(r0), "=r"(r1), "=r"(r2), "=r"(r3) : "r"(addr));
}
__device__ __forceinline__ void ldsm_x2(u32& r0, u32& r1, u32 addr) {
    asm volatile("ldmatrix.sync.aligned.m8n8.x2.shared.b16 {%0,%1}, [%2];"
                 : "=r"(r0), "=r"(r1) : "r"(addr));
}
__device__ __forceinline__ void mma_bf16(float* d, const u32* a, const u32* b) {
    asm volatile(
        "mma.sync.aligned.m16n8k16.row.col.f32.bf16.bf16.f32 "
        "{%0,%1,%2,%3}, {%4,%5,%6,%7}, {%8,%9}, {%0,%1,%2,%3};"
        : "+f"(d[0]), "+f"(d[1]), "+f"(d[2]), "+f"(d[3])
        : "r"(a[0]), "r"(a[1]), "r"(a[2]), "r"(a[3]), "r"(b[0]), "r"(b[1]));
}

__device__ __forceinline__ u32 sw128(u32 off) { return off ^ ((off >> 3) & 0x70); }

// bf16 split: v = hi + lo, both bf16
__device__ __forceinline__ void split_pack(float v0, float v1, u32& hi, u32& lo) {
    __nv_bfloat16 h0 = __float2bfloat16_rn(v0);
    __nv_bfloat16 h1 = __float2bfloat16_rn(v1);
    __nv_bfloat16 l0 = __float2bfloat16_rn(v0 - __bfloat162float(h0));
    __nv_bfloat16 l1 = __float2bfloat16_rn(v1 - __bfloat162float(h1));
    hi = (u32)__bfloat16_as_ushort(h0) | ((u32)__bfloat16_as_ushort(h1) << 16);
    lo = (u32)__bfloat16_as_ushort(l0) | ((u32)__bfloat16_as_ushort(l1) << 16);
}

// ================= tensor-core conv kernel (warp MMA, bf16x3 split) =================
// GEMM per CTA: D[128 co, 128 n] = sum_K A[co,k]*B[k,n], K ordered (tap, ci-chunk of 64).
// A smem: [128 m][64 k] bf16 (hi, lo); B smem: [128 n][64 k] bf16 (hi, lo). SW128 swizzle.
static constexpr int OFF_A_HI = 0;
static constexpr int OFF_A_LO = 16384;
static constexpr int OFF_B_HI = 32768;
static constexpr int OFF_B_LO = 49152;
static constexpr int SM_BYTES = 65536;

template <int CIN, int COUT, int VALID_M, int TAPS, int ACT, int PAD, bool ADDPROC>
__global__ void __launch_bounds__(512, 1)
mconv_kernel(const float* __restrict__ in, const float* __restrict__ w,
             const float* __restrict__ bias, float* __restrict__ out)
{
    constexpr int NCICH = CIN / 64;
    constexpr int NCHUNKS = TAPS * NCICH;

    extern __shared__ __align__(1024) char smem[];
    const u32 sb = smem_u32(smem);

    const int b   = blockIdx.z;
    const int co0 = blockIdx.y * 128;
    const int n0  = blockIdx.x * 128;
    const int t   = threadIdx.x;
    const int lane = t & 31;
    const int wrp  = t >> 5;        // 0..15
    const int wm   = wrp & 3;       // m group (32 rows)
    const int wn   = wrp >> 2;      // n group (32 cols)

    float acc[2][4][4];
#pragma unroll
    for (int i = 0; i < 2; i++)
#pragma unroll
        for (int j = 0; j < 4; j++)
#pragma unroll
            for (int c = 0; c < 4; c++) acc[i][j][c] = 0.f;

    const float* inB   = in + (size_t)b * CIN * 480u;
    const float* procB = g_proc + b * 256;

    for (int chunk = 0; chunk < NCHUNKS; ++chunk) {
        const int tap = chunk / NCICH;
        const int ci0 = (chunk % NCICH) * 64;
        const int ky  = tap / 3 - 1;
        const int kx  = tap % 3 - 1;

        __syncthreads();   // previous chunk's ldmatrix reads complete

        // ---- stage A: 128 m x 32 k2-pairs = 4096, 8 per thread ----
#pragma unroll
        for (int it = 0; it < 8; ++it) {
            int p  = it * 512 + t;
            int m  = p >> 5;
            int k2 = p & 31;
            int k  = k2 * 2;
            float v0 = 0.f, v1 = 0.f;
            if (VALID_M == 128 || m < VALID_M) {
                if (TAPS == 1) {
                    const float* wp = w + (size_t)(co0 + m) * CIN + ci0 + k;
                    v0 = wp[0]; v1 = wp[1];
                } else {
                    const float* wp = w + ((size_t)(co0 + m) * CIN + ci0 + k) * 9u + tap;
                    v0 = wp[0]; v1 = wp[9];
                }
            }
            u32 hi, lo;
            split_pack(v0, v1, hi, lo);
            u32 swo = sw128((u32)(m * 128 + k2 * 4));
            *(u32*)(smem + OFF_A_HI + swo) = hi;
            *(u32*)(smem + OFF_A_LO + swo) = lo;
        }

        // ---- stage B: 128 n x 32 k2-pairs = 4096, 8 per thread (n fastest for coalescing) ----
#pragma unroll
        for (int it = 0; it < 8; ++it) {
            int p  = it * 512 + t;
            int nl = p & 127;
            int k2 = p >> 7;
            int ci = ci0 + k2 * 2;
            int ng = n0 + nl;
            float v0 = 0.f, v1 = 0.f;
            if (ng < 480) {
                if (TAPS == 1) {
                    v0 = inB[(size_t)ci * 480u + ng];
                    v1 = inB[(size_t)(ci + 1) * 480u + ng];
                } else {
                    int r = ng / 40, c = ng - r * 40;
                    int ir = r + ky, ic = c + kx;
                    if (PAD == 0) {
                        if ((unsigned)ir < 12u && (unsigned)ic < 40u) {
                            int o = ir * 40 + ic;
                            v0 = inB[(size_t)ci * 480u + o];
                            v1 = inB[(size_t)(ci + 1) * 480u + o];
                            if (ADDPROC) { v0 += procB[ci]; v1 += procB[ci + 1]; }
                        }
                    } else {
                        if (ir < 0) ir = -ir;
                        if (ir >= 12) ir = 22 - ir;
                        if (ic < 0) ic = -ic;
                        if (ic >= 40) ic = 78 - ic;
                        int o = ir * 40 + ic;
                        v0 = inB[(size_t)ci * 480u + o];
                        v1 = inB[(size_t)(ci + 1) * 480u + o];
                        if (ADDPROC) { v0 += procB[ci]; v1 += procB[ci + 1]; }
                    }
                }
            }
            u32 hi, lo;
            split_pack(v0, v1, hi, lo);
            u32 swo = sw128((u32)(nl * 128 + k2 * 4));
            *(u32*)(smem + OFF_B_HI + swo) = hi;
            *(u32*)(smem + OFF_B_LO + swo) = lo;
        }

        __syncthreads();

        // ---- MMA phase: 3 passes (Ah*Bh, Ah*Bl, Al*Bh) ----
#pragma unroll
        for (int pass = 0; pass < 3; ++pass) {
            const u32 abase = sb + ((pass == 2) ? OFF_A_LO : OFF_A_HI);
            const u32 bbase = sb + ((pass == 1) ? OFF_B_LO : OFF_B_HI);
#pragma unroll
            for (int ks = 0; ks < 4; ++ks) {
                u32 af[2][4];
#pragma unroll
                for (int i = 0; i < 2; ++i) {
                    int row = wm * 32 + i * 16 + (lane & 7) + ((lane >> 3) & 1) * 8;
                    int col = ks * 16 + ((lane >> 4) & 1) * 8;
                    ldsm_x4(af[i][0], af[i][1], af[i][2], af[i][3],
                            abase + sw128((u32)(row * 128 + col * 2)));
                }
                u32 bf[4][2];
#pragma unroll
                for (int j = 0; j < 4; ++j) {
                    int row = wn * 32 + j * 8 + (lane & 7);
                    int col = ks * 16 + ((lane >> 3) & 1) * 8;
                    ldsm_x2(bf[j][0], bf[j][1],
                            bbase + sw128((u32)(row * 128 + col * 2)));
                }
#pragma unroll
                for (int i = 0; i < 2; ++i)
#pragma unroll
                    for (int j = 0; j < 4; ++j)
                        mma_bf16(acc[i][j], af[i], bf[j]);
            }
        }
    }

    // ---- epilogue: register accumulators -> global, bias + activation ----
    const int gid = lane >> 2;
    const int tig = lane & 3;
#pragma unroll
    for (int i = 0; i < 2; ++i) {
#pragma unroll
        for (int j = 0; j < 4; ++j) {
            int m = wm * 32 + i * 16 + gid;
            int n = n0 + wn * 32 + j * 8 + tig * 2;
            if (n >= 480) continue;
#pragma unroll
            for (int h = 0; h < 2; ++h) {        // h=0: row m; h=1: row m+8
                int mm = m + h * 8;
                if (VALID_M != 128 && mm >= VALID_M) continue;
                int co = co0 + mm;
                float bb = bias[co];
                float x0 = acc[i][j][2 * h]     + bb;
                float x1 = acc[i][j][2 * h + 1] + bb;
                if (ACT == 0) { x0 = fmaxf(x0, 0.f); x1 = fmaxf(x1, 0.f); }
                else {
                    x0 = (x0 > 0.f) ? x0 : expm1f(x0);
                    x1 = (x1 > 0.f) ? x1 : expm1f(x1);
                }
                float2 o; o.x = x0; o.y = x1;
                *reinterpret_cast<float2*>(out + ((size_t)b * COUT + co) * 480u + n) = o;
            }
        }
    }
}

// ---------------- generic mean-over-480 pool (one warp per row) ----------------
__global__ void pool_kernel(const float* __restrict__ src, float* __restrict__ dst, int rows)
{
    int r = blockIdx.x * 8 + (threadIdx.x >> 5);
    int lane = threadIdx.x & 31;
    if (r >= rows) return;
    const float* p = src + (size_t)r * 480u;
    float s = 0.f;
    for (int i = lane; i < 480; i += 32) s += p[i];
#pragma unroll
    for (int o = 16; o > 0; o >>= 1) s += __shfl_xor_sync(0xffffffffu, s, o);
    if (lane == 0) dst[r] = s * (1.0f / 480.0f);
}

// ---------------- feature bank inverse norms ----------------
__global__ void banknorm_kernel(const float* __restrict__ bank)
{
    int r = blockIdx.x * 8 + (threadIdx.x >> 5);
    int lane = threadIdx.x & 31;
    if (r >= 1000) return;
    float s = 0.f;
    for (int c = lane; c < 256; c += 32) {
        float v = bank[(size_t)r * 256u + c];
        s += v * v;
    }
#pragma unroll
    for (int o = 16; o > 0; o >>= 1) s += __shfl_xor_sync(0xffffffffu, s, o);
    if (lane == 0) g_bninv[r] = 1.0f / fmaxf(sqrtf(s), 1e-12f);
}

// ---------------- KNN + fusion MLP: one block per batch row ----------------
__global__ void knn_fusion_kernel(const float* __restrict__ bank,
                                  const float* __restrict__ W1, const float* __restrict__ b1,
                                  const float* __restrict__ W2, const float* __restrict__ b2)
{
    const int b = blockIdx.x;
    const int t = threadIdx.x;
    const int lane = t & 31;
    const int wid = t >> 5;

    __shared__ float q[256];
    __shared__ float sims[1000];
    __shared__ float red[8];
    __shared__ float rv[8]; __shared__ int ri[8];
    __shared__ float topv[5]; __shared__ int topi[5];
    __shared__ float wts[5];
    __shared__ float fused[512];
    __shared__ float h[256];

    q[t] = g_pooled[b * 256 + t];
    __syncthreads();

    float x = q[t] * q[t];
#pragma unroll
    for (int o = 16; o > 0; o >>= 1) x += __shfl_xor_sync(0xffffffffu, x, o);
    if (lane == 0) red[wid] = x;
    __syncthreads();
    if (t == 0) {
        float s = 0.f;
        for (int i = 0; i < 8; i++) s += red[i];
        red[0] = 1.0f / fmaxf(sqrtf(s), 1e-12f);
    }
    __syncthreads();
    const float qinv = red[0];

    for (int r = wid; r < 1000; r += 8) {
        float s = 0.f;
        const float* br = bank + (size_t)r * 256u;
        for (int c = lane; c < 256; c += 32) s += q[c] * br[c];
#pragma unroll
        for (int o = 16; o > 0; o >>= 1) s += __shfl_xor_sync(0xffffffffu, s, o);
        if (lane == 0) sims[r] = s * qinv * g_bninv[r];
    }
    __syncthreads();

    for (int k = 0; k < 5; k++) {
        float bv = -1e30f; int bi = 0x7fffffff;
        for (int r = t; r < 1000; r += 256) {
            float v = sims[r];
            if (v > bv || (v == bv && r < bi)) { bv = v; bi = r; }
        }
#pragma unroll
        for (int o = 16; o > 0; o >>= 1) {
            float ov = __shfl_xor_sync(0xffffffffu, bv, o);
            int oi   = __shfl_xor_sync(0xffffffffu, bi, o);
            if (ov > bv || (ov == bv && oi < bi)) { bv = ov; bi = oi; }
        }
        if (lane == 0) { rv[wid] = bv; ri[wid] = bi; }
        __syncthreads();
        if (t == 0) {
            float mv = rv[0]; int mi = ri[0];
            for (int i = 1; i < 8; i++)
                if (rv[i] > mv || (rv[i] == mv && ri[i] < mi)) { mv = rv[i]; mi = ri[i]; }
            topv[k] = mv; topi[k] = mi;
            sims[mi] = -1e30f;
        }
        __syncthreads();
    }

    if (t == 0) {
        float m = topv[0];
        float s = 0.f;
        for (int k = 0; k < 5; k++) { wts[k] = expf(topv[k] - m); s += wts[k]; }
        float inv = 1.0f / s;
        for (int k = 0; k < 5; k++) wts[k] *= inv;
    }
    __syncthreads();

    fused[t] = q[t];
    {
        float a = 0.f;
#pragma unroll
        for (int k = 0; k < 5; k++) a += wts[k] * bank[(size_t)topi[k] * 256u + t];
        fused[256 + t] = a;
    }
    __syncthreads();

    for (int j = wid; j < 256; j += 8) {
        float s = 0.f;
        const float* wr = W1 + (size_t)j * 512u;
        for (int i = lane; i < 512; i += 32) s += fused[i] * wr[i];
#pragma unroll
        for (int o = 16; o > 0; o >>= 1) s += __shfl_xor_sync(0xffffffffu, s, o);
        if (lane == 0) h[j] = fmaxf(s + b1[j], 0.f);
    }
    __syncthreads();

    for (int j = wid; j < 256; j += 8) {
        float s = 0.f;
        const float* wr = W2 + (size_t)j * 256u;
        for (int i = lane; i < 256; i += 32) s += h[i] * wr[i];
#pragma unroll
        for (int o = 16; o > 0; o >>= 1) s += __shfl_xor_sync(0xffffffffu, s, o);
        if (lane == 0) g_proc[b * 256 + j] = 0.1f * (s + b2[j]);
    }
}

// ---------------- pose2 (1x1 conv of pooled t1) ----------------
__global__ void pose2_kernel(const float* __restrict__ w, const float* __restrict__ bias)
{
    int b = blockIdx.x;
    int lane = threadIdx.x;   // block = 32
    const float* tp = g_t1pool + b * 256;
    for (int k = 0; k < 12; k++) {
        float s = 0.f;
        const float* wr = w + (size_t)k * 256u;
        for (int c = lane; c < 256; c += 32) s += tp[c] * wr[c];
#pragma unroll
        for (int o = 16; o > 0; o >>= 1) s += __shfl_xor_sync(0xffffffffu, s, o);
        if (lane == 0) g_out12[b * 12 + k] = s + bias[k];
    }
}

// ---------------- final: scale + pose outputs ----------------
__global__ void final_kernel(const float* __restrict__ lw, const float* __restrict__ lb,
                             float* __restrict__ outbuf)
{
    int b = threadIdx.x;   // 256 threads, 1 block
    float s = 0.f;
    const float* sf = g_sfeat + b * 64;
#pragma unroll
    for (int c = 0; c < 64; c++) s += sf[c] * lw[c];
    s += lb[0];
    float sig = 1.0f / (1.0f + expf(-s));
    float scale = expf(sig * (LOG_HI - LOG_LO) + LOG_LO);

    float* aa = outbuf;           // axisangle: (256,2,1,3)
    float* tr = outbuf + 1536;    // translation: (256,2,1,3)
#pragma unroll
    for (int u = 0; u < 2; u++) {
#pragma unroll
        for (int m = 0; m < 6; m++) {
            float v = 0.001f * g_out12[b * 12 + u * 6 + m] * scale;
            if (m < 3) aa[(b * 2 + u) * 3 + m]       = v;
            else       tr[(b * 2 + u) * 3 + (m - 3)] = v;
        }
    }
    outbuf[3072 + b] = scale;     // scale: (256,1)
}

// ---------------- launch ----------------
extern "C" void kernel_launch(void* const* d_in, const int* in_sizes, int n_in,
                              void* d_out, int out_size)
{
    (void)in_sizes; (void)n_in; (void)out_size;
    const float* f0         = (const float*)d_in[0];
    const float* squeeze_w  = (const float*)d_in[1];
    const float* squeeze_b  = (const float*)d_in[2];
    const float* pose0_w    = (const float*)d_in[3];
    const float* pose0_b    = (const float*)d_in[4];
    const float* pose1_w    = (const float*)d_in[5];
    const float* pose1_b    = (const float*)d_in[6];
    const float* pose2_w    = (const float*)d_in[7];
    const float* pose2_b    = (const float*)d_in[8];
    const float* fusion_w1  = (const float*)d_in[9];
    const float* fusion_b1  = (const float*)d_in[10];
    const float* fusion_w2  = (const float*)d_in[11];
    const float* fusion_b2  = (const float*)d_in[12];
    const float* bank       = (const float*)d_in[13];
    const float* scale_w1   = (const float*)d_in[14];
    const float* scale_b1   = (const float*)d_in[15];
    const float* scale_w2   = (const float*)d_in[16];
    const float* scale_b2   = (const float*)d_in[17];
    const float* scale_lw   = (const float*)d_in[18];
    const float* scale_lb   = (const float*)d_in[19];
    float* out = (float*)d_out;

    void *p_cat, *p_t0, *p_t1, *p_s1, *p_s2;
    cudaGetSymbolAddress(&p_cat, g_cat);
    cudaGetSymbolAddress(&p_t0,  g_t0);
    cudaGetSymbolAddress(&p_t1,  g_t1);
    cudaGetSymbolAddress(&p_s1,  g_s1);
    cudaGetSymbolAddress(&p_s2,  g_s2);
    void *p_pooled, *p_t1pool, *p_sfeat;
    cudaGetSymbolAddress(&p_pooled, g_pooled);
    cudaGetSymbolAddress(&p_t1pool, g_t1pool);
    cudaGetSymbolAddress(&p_sfeat,  g_sfeat);

    // conv instantiations: <CIN, COUT, VALID_M, TAPS, ACT, PAD, ADDPROC>
    auto k_sq = mconv_kernel<512, 256, 128, 1, 0, 0, false>;
    auto k_p0 = mconv_kernel<256, 256, 128, 9, 0, 0, true >;
    auto k_p1 = mconv_kernel<256, 256, 128, 9, 0, 0, false>;
    auto k_s1 = mconv_kernel<256, 128, 128, 9, 1, 1, true >;
    auto k_s2 = mconv_kernel<128,  64,  64, 9, 1, 1, false>;
    cudaFuncSetAttribute(k_sq, cudaFuncAttributeMaxDynamicSharedMemorySize, SM_BYTES);
    cudaFuncSetAttribute(k_p0, cudaFuncAttributeMaxDynamicSharedMemorySize, SM_BYTES);
    cudaFuncSetAttribute(k_p1, cudaFuncAttributeMaxDynamicSharedMemorySize, SM_BYTES);
    cudaFuncSetAttribute(k_s1, cudaFuncAttributeMaxDynamicSharedMemorySize, SM_BYTES);
    cudaFuncSetAttribute(k_s2, cudaFuncAttributeMaxDynamicSharedMemorySize, SM_BYTES);

    // squeeze + pooled
    k_sq<<<dim3(4, 2, 256), 512, SM_BYTES>>>(f0, squeeze_w, squeeze_b, (float*)p_cat);
    pool_kernel<<<(65536 + 7) / 8, 256>>>((const float*)p_cat, (float*)p_pooled, 65536);

    // KNN + fusion MLP -> g_proc (= 0.1*proc)
    banknorm_kernel<<<125, 256>>>(bank);
    knn_fusion_kernel<<<256, 256>>>(bank, fusion_w1, fusion_b1, fusion_w2, fusion_b2);

    // pose branch
    k_p0<<<dim3(4, 2, 256), 512, SM_BYTES>>>((const float*)p_cat, pose0_w, pose0_b, (float*)p_t0);
    k_p1<<<dim3(4, 2, 256), 512, SM_BYTES>>>((const float*)p_t0, pose1_w, pose1_b, (float*)p_t1);
    pool_kernel<<<(65536 + 7) / 8, 256>>>((const float*)p_t1, (float*)p_t1pool, 65536);
    pose2_kernel<<<256, 32>>>(pose2_w, pose2_b);

    // scale branch
    k_s1<<<dim3(4, 1, 256), 512, SM_BYTES>>>((const float*)p_cat, scale_w1, scale_b1, (float*)p_s1);
    k_s2<<<dim3(4, 1, 256), 512, SM_BYTES>>>((const float*)p_s1, scale_w2, scale_b2, (float*)p_s2);
    pool_kernel<<<(16384 + 7) / 8, 256>>>((const float*)p_s2, (float*)p_sfeat, 16384);

    // final assembly
    final_kernel<<<1, 256>>>(scale_lw, scale_lb, out);
}